// round 2
// baseline (speedup 1.0000x reference)
#include <cuda_runtime.h>
#include <cstdint>

#define HID 128
#define GATES 384           // 3*HID
#define HORIZON 60
#define TILE_B 32
#define THREADS 256
#define D_IN 256

// SMEM: wt [128][384] fp32 (W_hh transposed, k-major) = 192KB, h [32][128] = 16KB.
// Phase-1 x tile [32][256] = 32KB aliases the wt region.
#define SMEM_FLOATS (HID * GATES + TILE_B * HID)

#define PACK_F32X2(out, lo, hi) \
    asm("mov.b64 %0, {%1, %2};" : "=l"(out) : "r"(lo), "r"(hi))
#define UNPACK_F32X2(lo, hi, in) \
    asm("mov.b64 {%0, %1}, %2;" : "=r"(lo), "=r"(hi) : "l"(in))
#define FMA_F32X2(d, a, b, c) \
    asm("fma.rn.f32x2 %0, %1, %2, %3;" : "=l"(d) : "l"(a), "l"(b), "l"(c))

typedef unsigned long long u64;

__device__ __forceinline__ float fsig(float x) {
    x = fminf(fmaxf(x, -30.f), 30.f);
    return __fdividef(1.f, 1.f + __expf(-x));
}
__device__ __forceinline__ float ftanh(float x) {
    float a = fabsf(x);
    float e = __expf(-2.f * a);
    float t = __fdividef(1.f - e, 1.f + e);
    return copysignf(t, x);
}

__global__ void __launch_bounds__(THREADS, 1)
gru_traj_kernel(const float* __restrict__ x,
                const float* __restrict__ W_ih,
                const float* __restrict__ W_hh,
                const float* __restrict__ b_ih,
                const float* __restrict__ b_hh,
                const float* __restrict__ W_out,
                const float* __restrict__ b_out,
                float* __restrict__ out)
{
    extern __shared__ float smem[];
    float* wt = smem;                    // [HID][GATES]  (k-major, transposed W_hh)
    float* sh = smem + HID * GATES;      // [TILE_B][HID] h tile
    float* sx = smem;                    // [TILE_B][D_IN] phase-1 alias

    const int tid = threadIdx.x;
    const int tx = tid & 31;             // j-tile index (0..31) -> FULL 128 units
    const int ty = tid >> 5;             // row-tile index (0..7)
    const int r0 = ty * 4;               // 4 rows per thread (32 rows total)
    const int j0 = tx * 4;               // 4 hidden units per thread (128 total)
    const int rowbase = blockIdx.x * TILE_B;

    // ---------------- Phase 0: stage x tile in SMEM (coalesced) ----------------
    {
        const float4* xg = (const float4*)(x + (size_t)rowbase * D_IN);
        float4* sx4 = (float4*)sx;
        for (int i = tid; i < TILE_B * D_IN / 4; i += THREADS) sx4[i] = xg[i];
    }
    __syncthreads();

    // ---------------- Phase 1: gi = x @ W_ih^T (scalar; small vs recurrence) ----
    float gi[4][4][3];
    #pragma unroll
    for (int i = 0; i < 4; i++)
        #pragma unroll
        for (int jj = 0; jj < 4; jj++)
            #pragma unroll
            for (int g = 0; g < 3; g++) gi[i][jj][g] = 0.f;

    #pragma unroll 1
    for (int k = 0; k < D_IN; k += 4) {
        float4 hv[4];
        #pragma unroll
        for (int i = 0; i < 4; i++)
            hv[i] = *(const float4*)&sx[(r0 + i) * D_IN + k];
        #pragma unroll
        for (int g = 0; g < 3; g++) {
            #pragma unroll
            for (int jj = 0; jj < 4; jj++) {
                float4 w = *(const float4*)&W_ih[(size_t)(g * HID + j0 + jj) * D_IN + k];
                #pragma unroll
                for (int i = 0; i < 4; i++) {
                    float s = gi[i][jj][g];
                    s = fmaf(hv[i].x, w.x, s);
                    s = fmaf(hv[i].y, w.y, s);
                    s = fmaf(hv[i].z, w.z, s);
                    s = fmaf(hv[i].w, w.w, s);
                    gi[i][jj][g] = s;
                }
            }
        }
    }

    // biases: b_ih always; fold b_hh into r,z. b_hh_n stays separate (inside r*(...)).
    float bn[4];
    #pragma unroll
    for (int jj = 0; jj < 4; jj++) {
        #pragma unroll
        for (int g = 0; g < 3; g++) {
            float bb = b_ih[g * HID + j0 + jj] + (g < 2 ? b_hh[g * HID + j0 + jj] : 0.f);
            #pragma unroll
            for (int i = 0; i < 4; i++) gi[i][jj][g] += bb;
        }
        bn[jj] = b_hh[2 * HID + j0 + jj];
    }

    // Pack gi for r,z gates into f32x2 pairs (j-adjacent); keep gi_n scalar.
    u64 gi2[4][2][2];          // [i][jpair][gate r/z]
    float gin[4][4];
    #pragma unroll
    for (int i = 0; i < 4; i++) {
        #pragma unroll
        for (int jp = 0; jp < 2; jp++) {
            #pragma unroll
            for (int g = 0; g < 2; g++) {
                PACK_F32X2(gi2[i][jp][g],
                           __float_as_uint(gi[i][2 * jp][g]),
                           __float_as_uint(gi[i][2 * jp + 1][g]));
            }
        }
        #pragma unroll
        for (int jj = 0; jj < 4; jj++) gin[i][jj] = gi[i][jj][2];
    }

    // output head weights for this thread's j-slice
    float wo0[4], wo1[4], wo2[4];
    #pragma unroll
    for (int jj = 0; jj < 4; jj++) {
        wo0[jj] = W_out[0 * HID + j0 + jj];
        wo1[jj] = W_out[1 * HID + j0 + jj];
        wo2[jj] = W_out[2 * HID + j0 + jj];
    }
    const float bo0 = b_out[0], bo1 = b_out[1], bo2 = b_out[2];

    __syncthreads();   // done reading sx; wt overwrites that region

    // ---------------- Phase 2: stage W_hh transposed + zero h ----------------
    for (int idx = tid; idx < GATES * HID; idx += THREADS) {
        int g = idx >> 7;        // W_hh row (0..383), gate-major
        int k = idx & 127;       // W_hh col (0..127)
        wt[k * GATES + g] = W_hh[idx];   // coalesced global read
    }
    for (int idx = tid; idx < TILE_B * HID; idx += THREADS) sh[idx] = 0.f;
    __syncthreads();

    // ---------------- Phase 3: 60 recurrence steps ----------------
    for (int t = 0; t < HORIZON; t++) {
        // acc2[i][jpair][gate]: gates r,z start from gi (b_hh folded); gate n from 0.
        u64 acc2[4][2][3];
        #pragma unroll
        for (int i = 0; i < 4; i++)
            #pragma unroll
            for (int jp = 0; jp < 2; jp++) {
                acc2[i][jp][0] = gi2[i][jp][0];
                acc2[i][jp][1] = gi2[i][jp][1];
                acc2[i][jp][2] = 0ull;
            }

        #pragma unroll 1
        for (int k = 0; k < HID; k += 4) {
            float4 hv[4];
            #pragma unroll
            for (int i = 0; i < 4; i++)
                hv[i] = *(const float4*)&sh[(r0 + i) * HID + k];
            #pragma unroll
            for (int kk = 0; kk < 4; kk++) {
                const float* wrow = &wt[(k + kk) * GATES + j0];
                ulonglong2 wr = *(const ulonglong2*)(wrow);            // r: j pairs
                ulonglong2 wz = *(const ulonglong2*)(wrow + HID);      // z
                ulonglong2 wn = *(const ulonglong2*)(wrow + 2 * HID);  // n
                #pragma unroll
                for (int i = 0; i < 4; i++) {
                    float h = (kk == 0) ? hv[i].x : (kk == 1) ? hv[i].y
                             : (kk == 2) ? hv[i].z : hv[i].w;
                    u64 hb;
                    uint32_t hu = __float_as_uint(h);
                    PACK_F32X2(hb, hu, hu);
                    FMA_F32X2(acc2[i][0][0], hb, wr.x, acc2[i][0][0]);
                    FMA_F32X2(acc2[i][1][0], hb, wr.y, acc2[i][1][0]);
                    FMA_F32X2(acc2[i][0][1], hb, wz.x, acc2[i][0][1]);
                    FMA_F32X2(acc2[i][1][1], hb, wz.y, acc2[i][1][1]);
                    FMA_F32X2(acc2[i][0][2], hb, wn.x, acc2[i][0][2]);
                    FMA_F32X2(acc2[i][1][2], hb, wn.y, acc2[i][1][2]);
                }
            }
        }

        // epilogue: activations + GRU update (scalar)
        float hn[4][4];
        #pragma unroll
        for (int i = 0; i < 4; i++) {
            float4 holdv = *(const float4*)&sh[(r0 + i) * HID + j0];
            float holds[4] = {holdv.x, holdv.y, holdv.z, holdv.w};
            #pragma unroll
            for (int jp = 0; jp < 2; jp++) {
                uint32_t rl, rh, zl, zh, nl, nh;
                UNPACK_F32X2(rl, rh, acc2[i][jp][0]);
                UNPACK_F32X2(zl, zh, acc2[i][jp][1]);
                UNPACK_F32X2(nl, nh, acc2[i][jp][2]);
                #pragma unroll
                for (int half = 0; half < 2; half++) {
                    int jj = 2 * jp + half;
                    float pr = __uint_as_float(half ? rh : rl);
                    float pz = __uint_as_float(half ? zh : zl);
                    float pn = __uint_as_float(half ? nh : nl);
                    float rr = fsig(pr);
                    float zz = fsig(pz);
                    float nnv = ftanh(fmaf(rr, pn + bn[jj], gin[i][jj]));
                    hn[i][jj] = nnv + zz * (holds[jj] - nnv);   // (1-z)n + z h
                }
            }
        }
        __syncthreads();   // all reads of old h complete
        #pragma unroll
        for (int i = 0; i < 4; i++) {
            *(float4*)&sh[(r0 + i) * HID + j0] =
                make_float4(hn[i][0], hn[i][1], hn[i][2], hn[i][3]);
        }
        __syncthreads();   // new h visible

        // output head: out[b, t, :] = h_new @ W_out^T + b_out
        // one warp == one row group (ty); 32 lanes cover all 128 units -> full-warp reduce
        #pragma unroll
        for (int i = 0; i < 4; i++) {
            float p0 = 0.f, p1 = 0.f, p2 = 0.f;
            #pragma unroll
            for (int jj = 0; jj < 4; jj++) {
                p0 = fmaf(hn[i][jj], wo0[jj], p0);
                p1 = fmaf(hn[i][jj], wo1[jj], p1);
                p2 = fmaf(hn[i][jj], wo2[jj], p2);
            }
            #pragma unroll
            for (int m = 16; m >= 1; m >>= 1) {
                p0 += __shfl_xor_sync(0xFFFFFFFFu, p0, m);
                p1 += __shfl_xor_sync(0xFFFFFFFFu, p1, m);
                p2 += __shfl_xor_sync(0xFFFFFFFFu, p2, m);
            }
            if (tx == 0) {
                float* op = out + (size_t)(rowbase + r0 + i) * (HORIZON * 3) + t * 3;
                op[0] = p0 + bo0;
                op[1] = p1 + bo1;
                op[2] = p2 + bo2;
            }
        }
    }
}

extern "C" void kernel_launch(void* const* d_in, const int* in_sizes, int n_in,
                              void* d_out, int out_size) {
    const float* x     = (const float*)d_in[0];
    const float* W_ih  = (const float*)d_in[1];
    const float* W_hh  = (const float*)d_in[2];
    const float* b_ih  = (const float*)d_in[3];
    const float* b_hh  = (const float*)d_in[4];
    const float* W_out = (const float*)d_in[5];
    const float* b_out = (const float*)d_in[6];
    float* out = (float*)d_out;

    const int B = in_sizes[0] / D_IN;          // 16384
    const size_t smem_bytes = (size_t)SMEM_FLOATS * sizeof(float);  // 212992

    cudaFuncSetAttribute(gru_traj_kernel,
                         cudaFuncAttributeMaxDynamicSharedMemorySize,
                         (int)smem_bytes);

    gru_traj_kernel<<<B / TILE_B, THREADS, smem_bytes>>>(
        x, W_ih, W_hh, b_ih, b_hh, W_out, b_out, out);
}

// round 3
// speedup vs baseline: 1.0682x; 1.0682x over previous
#include <cuda_runtime.h>
#include <cstdint>

#define HID 128
#define GATES 384           // 3*HID
#define HORIZON 60
#define TILE_B 32
#define THREADS 256
#define D_IN 256

#define ST_H 36             // sh_t row stride (floats): conflict-free h loads
#define ST_X 260            // sx row stride (floats)

// SMEM floats: wt[128][384] = 49152 | sh_t[128][36] = 4608 | sred[4][32][3] = 384
#define OFF_SHT   (HID * GATES)
#define OFF_SRED  (OFF_SHT + HID * ST_H)
#define SMEM_FLOATS (OFF_SRED + 4 * TILE_B * 3)

#define PACK_F32X2(out, lo, hi) \
    asm("mov.b64 %0, {%1, %2};" : "=l"(out) : "r"(lo), "r"(hi))
#define UNPACK_F32X2(lo, hi, in) \
    asm("mov.b64 {%0, %1}, %2;" : "=r"(lo), "=r"(hi) : "l"(in))
#define FMA_F32X2(d, a, b, c) \
    asm("fma.rn.f32x2 %0, %1, %2, %3;" : "=l"(d) : "l"(a), "l"(b), "l"(c))

typedef unsigned long long u64;

__device__ __forceinline__ float fsig(float x) {
    x = fminf(fmaxf(x, -30.f), 30.f);
    return __fdividef(1.f, 1.f + __expf(-x));
}
__device__ __forceinline__ float ftanh(float x) {
    float a = fabsf(x);
    float e = __expf(-2.f * a);
    float t = __fdividef(1.f - e, 1.f + e);
    return copysignf(t, x);
}

__global__ void __launch_bounds__(THREADS, 1)
gru_traj_kernel(const float* __restrict__ x,
                const float* __restrict__ W_ih,
                const float* __restrict__ W_hh,
                const float* __restrict__ b_ih,
                const float* __restrict__ b_hh,
                const float* __restrict__ W_out,
                const float* __restrict__ b_out,
                float* __restrict__ out)
{
    extern __shared__ float smem[];
    float* wt   = smem;              // [HID][GATES]  k-major transposed W_hh
    float* sh_t = smem + OFF_SHT;    // [HID][ST_H]   h transposed: [unit][row]
    float* sred = smem + OFF_SRED;   // [4][TILE_B][3] output partials per jq
    float* sx   = smem;              // [TILE_B][ST_X] phase-1 alias of wt

    const int tid   = threadIdx.x;
    const int lane  = tid & 31;
    const int warp  = tid >> 5;
    const int jq    = warp & 3;          // j-quarter (0..3)
    const int rh    = warp >> 2;         // row half (0..1)
    const int jlane = lane & 7;          // 8 j-groups within quarter
    const int rlane = lane >> 3;         // 4 row-groups within half
    const int j0 = jq * 32 + jlane * 4;  // 4 hidden units per thread
    const int r0 = rh * 16 + rlane * 4;  // 4 rows per thread
    const int rowbase = blockIdx.x * TILE_B;

    // ---------------- Phase 0: stage x tile in padded SMEM ----------------
    for (int idx = tid; idx < TILE_B * (D_IN / 4); idx += THREADS) {
        int row = idx >> 6;          // /64
        int c4  = idx & 63;
        *(float4*)&sx[row * ST_X + c4 * 4] =
            ((const float4*)(x + (size_t)rowbase * D_IN))[idx];
    }
    __syncthreads();

    // ---------------- Phase 1: gi = x @ W_ih^T ----------------
    float gi[4][4][3];
    #pragma unroll
    for (int i = 0; i < 4; i++)
        #pragma unroll
        for (int jj = 0; jj < 4; jj++)
            #pragma unroll
            for (int g = 0; g < 3; g++) gi[i][jj][g] = 0.f;

    #pragma unroll 1
    for (int k = 0; k < D_IN; k += 4) {
        float4 hv[4];
        #pragma unroll
        for (int i = 0; i < 4; i++)
            hv[i] = *(const float4*)&sx[(r0 + i) * ST_X + k];
        #pragma unroll
        for (int g = 0; g < 3; g++) {
            #pragma unroll
            for (int jj = 0; jj < 4; jj++) {
                float4 w = *(const float4*)&W_ih[(size_t)(g * HID + j0 + jj) * D_IN + k];
                #pragma unroll
                for (int i = 0; i < 4; i++) {
                    float s = gi[i][jj][g];
                    s = fmaf(hv[i].x, w.x, s);
                    s = fmaf(hv[i].y, w.y, s);
                    s = fmaf(hv[i].z, w.z, s);
                    s = fmaf(hv[i].w, w.w, s);
                    gi[i][jj][g] = s;
                }
            }
        }
    }

    // biases: b_ih always; fold b_hh into r,z. b_hh_n stays separate.
    float bn[4];
    #pragma unroll
    for (int jj = 0; jj < 4; jj++) {
        #pragma unroll
        for (int g = 0; g < 3; g++) {
            float bb = b_ih[g * HID + j0 + jj] + (g < 2 ? b_hh[g * HID + j0 + jj] : 0.f);
            #pragma unroll
            for (int i = 0; i < 4; i++) gi[i][jj][g] += bb;
        }
        bn[jj] = b_hh[2 * HID + j0 + jj];
    }

    // pack gi r,z as f32x2 j-pairs; keep gi_n scalar
    u64 gi2[4][2][2];
    float gin[4][4];
    #pragma unroll
    for (int i = 0; i < 4; i++) {
        #pragma unroll
        for (int jp = 0; jp < 2; jp++)
            #pragma unroll
            for (int g = 0; g < 2; g++)
                PACK_F32X2(gi2[i][jp][g],
                           __float_as_uint(gi[i][2 * jp][g]),
                           __float_as_uint(gi[i][2 * jp + 1][g]));
        #pragma unroll
        for (int jj = 0; jj < 4; jj++) gin[i][jj] = gi[i][jj][2];
    }

    // output head weights for this thread's 4 units
    float wo0[4], wo1[4], wo2[4];
    #pragma unroll
    for (int jj = 0; jj < 4; jj++) {
        wo0[jj] = W_out[0 * HID + j0 + jj];
        wo1[jj] = W_out[1 * HID + j0 + jj];
        wo2[jj] = W_out[2 * HID + j0 + jj];
    }
    const float bo0 = b_out[0], bo1 = b_out[1], bo2 = b_out[2];

    __syncthreads();   // done with sx; wt overwrites

    // ---------------- Phase 2: stage W_hh transposed; zero sh_t ----------------
    for (int idx = tid; idx < GATES * HID; idx += THREADS) {
        int g = idx >> 7;          // W_hh row (gate-output index)
        int k = idx & 127;         // W_hh col
        wt[k * GATES + g] = W_hh[idx];
    }
    for (int idx = tid; idx < HID * ST_H; idx += THREADS) sh_t[idx] = 0.f;
    __syncthreads();

    // h_old lives in registers (thread tile is fixed across steps)
    float hprev[4][4];
    #pragma unroll
    for (int i = 0; i < 4; i++)
        #pragma unroll
        for (int jj = 0; jj < 4; jj++) hprev[i][jj] = 0.f;

    // ---------------- Phase 3: recurrence ----------------
    for (int t = 0; t < HORIZON; t++) {
        u64 acc2[4][2][3];
        #pragma unroll
        for (int i = 0; i < 4; i++)
            #pragma unroll
            for (int jp = 0; jp < 2; jp++) {
                acc2[i][jp][0] = gi2[i][jp][0];
                acc2[i][jp][1] = gi2[i][jp][1];
                acc2[i][jp][2] = 0ull;
            }

        if (t) {
            #pragma unroll 4
            for (int k = 0; k < HID; k++) {
                // h for 4 rows at unit k: conflict-free float4
                float4 hv = *(const float4*)&sh_t[k * ST_H + r0];
                const float* wrow = &wt[k * GATES + j0];
                ulonglong2 wr = *(const ulonglong2*)(wrow);
                ulonglong2 wz = *(const ulonglong2*)(wrow + HID);
                ulonglong2 wn = *(const ulonglong2*)(wrow + 2 * HID);
                float hs[4] = {hv.x, hv.y, hv.z, hv.w};
                #pragma unroll
                for (int i = 0; i < 4; i++) {
                    u64 hb;
                    uint32_t hu = __float_as_uint(hs[i]);
                    PACK_F32X2(hb, hu, hu);
                    FMA_F32X2(acc2[i][0][0], hb, wr.x, acc2[i][0][0]);
                    FMA_F32X2(acc2[i][1][0], hb, wr.y, acc2[i][1][0]);
                    FMA_F32X2(acc2[i][0][1], hb, wz.x, acc2[i][0][1]);
                    FMA_F32X2(acc2[i][1][1], hb, wz.y, acc2[i][1][1]);
                    FMA_F32X2(acc2[i][0][2], hb, wn.x, acc2[i][0][2]);
                    FMA_F32X2(acc2[i][1][2], hb, wn.y, acc2[i][1][2]);
                }
            }
        }

        // epilogue: activations + GRU update (h_old from registers)
        float hn[4][4];
        #pragma unroll
        for (int i = 0; i < 4; i++) {
            #pragma unroll
            for (int jp = 0; jp < 2; jp++) {
                uint32_t rl, rhh, zl, zh, nl, nh;
                UNPACK_F32X2(rl, rhh, acc2[i][jp][0]);
                UNPACK_F32X2(zl, zh,  acc2[i][jp][1]);
                UNPACK_F32X2(nl, nh,  acc2[i][jp][2]);
                #pragma unroll
                for (int half = 0; half < 2; half++) {
                    int jj = 2 * jp + half;
                    float pr = __uint_as_float(half ? rhh : rl);
                    float pz = __uint_as_float(half ? zh : zl);
                    float pn = __uint_as_float(half ? nh : nl);
                    float rr = fsig(pr);
                    float zz = fsig(pz);
                    float nnv = ftanh(fmaf(rr, pn + bn[jj], gin[i][jj]));
                    hn[i][jj] = nnv + zz * (hprev[i][jj] - nnv);
                }
            }
        }

        __syncthreads();   // mainloop reads of old sh_t complete everywhere

        // store new h (transposed) + output partials
        #pragma unroll
        for (int jj = 0; jj < 4; jj++) {
            *(float4*)&sh_t[(j0 + jj) * ST_H + r0] =
                make_float4(hn[0][jj], hn[1][jj], hn[2][jj], hn[3][jj]);
        }
        #pragma unroll
        for (int i = 0; i < 4; i++) {
            float p0 = 0.f, p1 = 0.f, p2 = 0.f;
            #pragma unroll
            for (int jj = 0; jj < 4; jj++) {
                p0 = fmaf(hn[i][jj], wo0[jj], p0);
                p1 = fmaf(hn[i][jj], wo1[jj], p1);
                p2 = fmaf(hn[i][jj], wo2[jj], p2);
            }
            #pragma unroll
            for (int m = 4; m >= 1; m >>= 1) {   // reduce over jlane (xor 1,2,4)
                p0 += __shfl_xor_sync(0xFFFFFFFFu, p0, m);
                p1 += __shfl_xor_sync(0xFFFFFFFFu, p1, m);
                p2 += __shfl_xor_sync(0xFFFFFFFFu, p2, m);
            }
            if (jlane == 0) {
                float* sp = &sred[(jq * TILE_B + r0 + i) * 3];
                sp[0] = p0; sp[1] = p1; sp[2] = p2;
            }
            #pragma unroll
            for (int jj = 0; jj < 4; jj++) hprev[i][jj] = hn[i][jj];
        }

        __syncthreads();   // new h + partials visible

        // finalize output head: sum 4 jq partials, add bias, write gmem
        if (tid < TILE_B * 3) {
            int row = tid / 3, o = tid % 3;
            float v = sred[(0 * TILE_B + row) * 3 + o]
                    + sred[(1 * TILE_B + row) * 3 + o]
                    + sred[(2 * TILE_B + row) * 3 + o]
                    + sred[(3 * TILE_B + row) * 3 + o];
            v += (o == 0) ? bo0 : (o == 1) ? bo1 : bo2;
            out[(size_t)(rowbase + row) * (HORIZON * 3) + t * 3 + o] = v;
        }
    }
}

extern "C" void kernel_launch(void* const* d_in, const int* in_sizes, int n_in,
                              void* d_out, int out_size) {
    const float* x     = (const float*)d_in[0];
    const float* W_ih  = (const float*)d_in[1];
    const float* W_hh  = (const float*)d_in[2];
    const float* b_ih  = (const float*)d_in[3];
    const float* b_hh  = (const float*)d_in[4];
    const float* W_out = (const float*)d_in[5];
    const float* b_out = (const float*)d_in[6];
    float* out = (float*)d_out;

    const int B = in_sizes[0] / D_IN;          // 16384
    const size_t smem_bytes = (size_t)SMEM_FLOATS * sizeof(float);  // ~216.6 KB

    cudaFuncSetAttribute(gru_traj_kernel,
                         cudaFuncAttributeMaxDynamicSharedMemorySize,
                         (int)smem_bytes);

    gru_traj_kernel<<<B / TILE_B, THREADS, smem_bytes>>>(
        x, W_ih, W_hh, b_ih, b_hh, W_out, b_out, out);
}

// round 14
// speedup vs baseline: 1.3938x; 1.3048x over previous
#include <cuda_runtime.h>
#include <cuda_bf16.h>
#include <cstdint>

#define HID 128
#define HORIZON 60
#define THREADS 256
#define D_IN 256
#define M_TILE 128
#define B_TOTAL 16384

#define W_STRIDE 272                 // padded W row: 136 bf16 = 272 B (conflict-free ldmatrix)
#define SOFF_WOUT4 0                 // 128 * float4 {w0,w1,w2,b_hh_n}
#define SOFF_WHI   2048
#define SOFF_WLO   (2048 + 384 * W_STRIDE)
#define SMEM_BYTES (2048 + 2 * 384 * W_STRIDE)   // 210944
#define ST_X 260                     // phase-1 x row stride (floats)

__device__ float g_gi[(size_t)B_TOTAL * 384];    // [row][384]: r,z (+b_ih+b_hh), n (+b_ih)

static __device__ __forceinline__ uint32_t smem_u32(const void* p) {
    uint32_t a;
    asm("{ .reg .u64 t; cvta.to.shared.u64 t, %1; cvt.u32.u64 %0, t; }" : "=r"(a) : "l"(p));
    return a;
}
static __device__ __forceinline__ void ldsm_x2(uint32_t* r, uint32_t addr) {
    asm volatile("ldmatrix.sync.aligned.m8n8.x2.shared.b16 {%0,%1}, [%2];"
        : "=r"(r[0]), "=r"(r[1]) : "r"(addr));
}
static __device__ __forceinline__ void mma16816(float* c, const uint32_t* a, const uint32_t* b) {
    asm volatile(
        "mma.sync.aligned.m16n8k16.row.col.f32.bf16.bf16.f32 "
        "{%0,%1,%2,%3}, {%4,%5,%6,%7}, {%8,%9}, {%0,%1,%2,%3};"
        : "+f"(c[0]), "+f"(c[1]), "+f"(c[2]), "+f"(c[3])
        : "r"(a[0]), "r"(a[1]), "r"(a[2]), "r"(a[3]), "r"(b[0]), "r"(b[1]));
}
static __device__ __forceinline__ uint32_t pkbf(float lo, float hi) {   // lo -> bits[0:16)
    uint32_t r;
    asm("cvt.rn.bf16x2.f32 %0, %1, %2;" : "=r"(r) : "f"(hi), "f"(lo));
    return r;
}
static __device__ __forceinline__ float2 unpk2(uint32_t h, uint32_t l) {
    float lo = __bfloat162float(__ushort_as_bfloat16((unsigned short)(h & 0xffff)))
             + __bfloat162float(__ushort_as_bfloat16((unsigned short)(l & 0xffff)));
    float hi = __bfloat162float(__ushort_as_bfloat16((unsigned short)(h >> 16)))
             + __bfloat162float(__ushort_as_bfloat16((unsigned short)(l >> 16)));
    return make_float2(lo, hi);
}
__device__ __forceinline__ float fsig(float x) {
    x = fminf(fmaxf(x, -30.f), 30.f);
    return __fdividef(1.f, 1.f + __expf(-x));
}
__device__ __forceinline__ float ftanh(float x) {
    float a = fabsf(x);
    float e = __expf(-2.f * a);
    float t = __fdividef(1.f - e, 1.f + e);
    return copysignf(t, x);
}

// One GRU step for this warp's 16 rows. Reads A(cur)=h_{t-1} frags, writes A(nxt)=h_t frags.
static __device__ __forceinline__ void gru_step(
    int t, bool first,
    uint32_t (*Ach)[4], uint32_t (*Acl)[4],
    uint32_t (*Anh)[4], uint32_t (*Anl)[4],
    uint32_t sb, uint32_t lane_off, int lane,
    const float* gp_lo, const float* gp_hi,
    const float4* wout4, float* outp_lo, float* outp_hi,
    float bo0, float bo1, float bo2)
{
    float pl0 = 0.f, pl1 = 0.f, pl2 = 0.f, ph0 = 0.f, ph1 = 0.f, ph2 = 0.f;

    #pragma unroll
    for (int c = 0; c < 4; c++) {
        float C[3][4][4];
        float gin[4][4];
        #pragma unroll
        for (int jt = 0; jt < 4; jt++) {
            int jc = 32 * c + 8 * jt + 2 * (lane & 3);
            float2 a0 = *(const float2*)(gp_lo + jc);
            float2 a1 = *(const float2*)(gp_hi + jc);
            C[0][jt][0] = a0.x; C[0][jt][1] = a0.y; C[0][jt][2] = a1.x; C[0][jt][3] = a1.y;
            float2 b0 = *(const float2*)(gp_lo + 128 + jc);
            float2 b1 = *(const float2*)(gp_hi + 128 + jc);
            C[1][jt][0] = b0.x; C[1][jt][1] = b0.y; C[1][jt][2] = b1.x; C[1][jt][3] = b1.y;
            C[2][jt][0] = 0.f; C[2][jt][1] = 0.f; C[2][jt][2] = 0.f; C[2][jt][3] = 0.f;
            float2 n0 = *(const float2*)(gp_lo + 256 + jc);
            float2 n1 = *(const float2*)(gp_hi + 256 + jc);
            gin[jt][0] = n0.x; gin[jt][1] = n0.y; gin[jt][2] = n1.x; gin[jt][3] = n1.y;
        }

        if (!first) {
            #pragma unroll
            for (int s = 0; s < 8; s++) {
                #pragma unroll
                for (int g = 0; g < 3; g++) {
                    #pragma unroll
                    for (int jt = 0; jt < 4; jt++) {
                        uint32_t off = (uint32_t)((g * 128 + 32 * c + 8 * jt) * W_STRIDE + s * 32)
                                     + lane_off;
                        uint32_t bh[2], bl[2];
                        ldsm_x2(bh, sb + SOFF_WHI + off);
                        ldsm_x2(bl, sb + SOFF_WLO + off);
                        mma16816(C[g][jt], Ach[s], bh);   // h_hi * W_hi
                        mma16816(C[g][jt], Acl[s], bh);   // h_lo * W_hi
                        mma16816(C[g][jt], Ach[s], bl);   // h_hi * W_lo
                    }
                }
            }
        }

        #pragma unroll
        for (int jt = 0; jt < 4; jt++) {
            int j0 = 32 * c + 8 * jt + 2 * (lane & 3);
            float4 w4a = wout4[j0];
            float4 w4b = wout4[j0 + 1];
            int s = 2 * c + (jt >> 1);
            int ai = (jt & 1) * 2;
            float hp[4];
            if (!first) {
                float2 u0 = unpk2(Ach[s][ai], Acl[s][ai]);
                float2 u1 = unpk2(Ach[s][ai + 1], Acl[s][ai + 1]);
                hp[0] = u0.x; hp[1] = u0.y; hp[2] = u1.x; hp[3] = u1.y;
            } else {
                hp[0] = hp[1] = hp[2] = hp[3] = 0.f;
            }
            float hn[4];
            #pragma unroll
            for (int i = 0; i < 4; i++) {
                float bhn = (i & 1) ? w4b.w : w4a.w;
                float r = fsig(C[0][jt][i]);
                float z = fsig(C[1][jt][i]);
                float nn = ftanh(fmaf(r, C[2][jt][i] + bhn, gin[jt][i]));
                hn[i] = nn + z * (hp[i] - nn);
            }
            pl0 = fmaf(hn[0], w4a.x, fmaf(hn[1], w4b.x, pl0));
            pl1 = fmaf(hn[0], w4a.y, fmaf(hn[1], w4b.y, pl1));
            pl2 = fmaf(hn[0], w4a.z, fmaf(hn[1], w4b.z, pl2));
            ph0 = fmaf(hn[2], w4a.x, fmaf(hn[3], w4b.x, ph0));
            ph1 = fmaf(hn[2], w4a.y, fmaf(hn[3], w4b.y, ph1));
            ph2 = fmaf(hn[2], w4a.z, fmaf(hn[3], w4b.z, ph2));
            // pack h_t into next A frags (bf16 hi + residual lo)
            float r0 = hn[0] - __bfloat162float(__float2bfloat16(hn[0]));
            float r1 = hn[1] - __bfloat162float(__float2bfloat16(hn[1]));
            float r2 = hn[2] - __bfloat162float(__float2bfloat16(hn[2]));
            float r3 = hn[3] - __bfloat162float(__float2bfloat16(hn[3]));
            Anh[s][ai]     = pkbf(hn[0], hn[1]);
            Anh[s][ai + 1] = pkbf(hn[2], hn[3]);
            Anl[s][ai]     = pkbf(r0, r1);
            Anl[s][ai + 1] = pkbf(r2, r3);
        }
    }

    #pragma unroll
    for (int m = 1; m <= 2; m <<= 1) {
        pl0 += __shfl_xor_sync(0xFFFFFFFFu, pl0, m);
        pl1 += __shfl_xor_sync(0xFFFFFFFFu, pl1, m);
        pl2 += __shfl_xor_sync(0xFFFFFFFFu, pl2, m);
        ph0 += __shfl_xor_sync(0xFFFFFFFFu, ph0, m);
        ph1 += __shfl_xor_sync(0xFFFFFFFFu, ph1, m);
        ph2 += __shfl_xor_sync(0xFFFFFFFFu, ph2, m);
    }
    if ((lane & 3) == 0) {
        float* o = outp_lo + 3 * t;
        o[0] = pl0 + bo0; o[1] = pl1 + bo1; o[2] = pl2 + bo2;
        float* o2 = outp_hi + 3 * t;
        o2[0] = ph0 + bo0; o2[1] = ph1 + bo1; o2[2] = ph2 + bo2;
    }
}

__global__ void __launch_bounds__(THREADS, 1)
gru_hmma_kernel(const float* __restrict__ x,
                const float* __restrict__ W_ih,
                const float* __restrict__ W_hh,
                const float* __restrict__ b_ih,
                const float* __restrict__ b_hh,
                const float* __restrict__ W_out,
                const float* __restrict__ b_out,
                float* __restrict__ out)
{
    extern __shared__ char smem[];
    float* sx = (float*)smem;                        // phase-1 alias
    const uint32_t sb = smem_u32(smem);
    const int tid = threadIdx.x, lane = tid & 31, w = tid >> 5;
    const int rowbase = blockIdx.x * M_TILE;

    // ================= Phase 1: gi = x @ W_ih^T + biases -> g_gi (SIMT fp32) =========
    for (int idx = tid; idx < M_TILE * (D_IN / 4); idx += THREADS) {
        int row = idx >> 6, c4 = idx & 63;
        *(float4*)&sx[row * ST_X + c4 * 4] =
            ((const float4*)(x + (size_t)rowbase * D_IN))[idx];
    }
    __syncthreads();
    {
        const int tx = tid & 31, ty5 = tid >> 5;
        const int j0 = tx * 4;
        for (int q = 0; q < 4; q++) {
            int r0 = q * 32 + ty5 * 4;
            float acc[4][4][3];
            #pragma unroll
            for (int i = 0; i < 4; i++)
                #pragma unroll
                for (int jj = 0; jj < 4; jj++)
                    #pragma unroll
                    for (int g = 0; g < 3; g++) acc[i][jj][g] = 0.f;
            #pragma unroll 1
            for (int k = 0; k < D_IN; k += 4) {
                float4 xv[4];
                #pragma unroll
                for (int i = 0; i < 4; i++) xv[i] = *(const float4*)&sx[(r0 + i) * ST_X + k];
                #pragma unroll
                for (int g = 0; g < 3; g++) {
                    #pragma unroll
                    for (int jj = 0; jj < 4; jj++) {
                        float4 wv = *(const float4*)&W_ih[(size_t)(g * 128 + j0 + jj) * D_IN + k];
                        #pragma unroll
                        for (int i = 0; i < 4; i++) {
                            float s = acc[i][jj][g];
                            s = fmaf(xv[i].x, wv.x, s);
                            s = fmaf(xv[i].y, wv.y, s);
                            s = fmaf(xv[i].z, wv.z, s);
                            s = fmaf(xv[i].w, wv.w, s);
                            acc[i][jj][g] = s;
                        }
                    }
                }
            }
            #pragma unroll
            for (int i = 0; i < 4; i++) {
                #pragma unroll
                for (int g = 0; g < 3; g++) {
                    float4 st;
                    float* stp = &st.x;
                    #pragma unroll
                    for (int jj = 0; jj < 4; jj++) {
                        float bb = b_ih[g * 128 + j0 + jj] + (g < 2 ? b_hh[g * 128 + j0 + jj] : 0.f);
                        stp[jj] = acc[i][jj][g] + bb;
                    }
                    *(float4*)&g_gi[(size_t)(rowbase + r0 + i) * 384 + g * 128 + j0] = st;
                }
            }
        }
    }
    __syncthreads();

    // ================= Stage W_hh (bf16 hi/lo, padded rows) + wout4 table ============
    for (int idx = tid; idx < 384 * 128; idx += THREADS) {
        int n = idx >> 7, k = idx & 127;
        float wv = W_hh[idx];
        __nv_bfloat16 bh = __float2bfloat16(wv);
        __nv_bfloat16 bl = __float2bfloat16(wv - __bfloat162float(bh));
        *(__nv_bfloat16*)(smem + SOFF_WHI + n * W_STRIDE + k * 2) = bh;
        *(__nv_bfloat16*)(smem + SOFF_WLO + n * W_STRIDE + k * 2) = bl;
    }
    for (int j = tid; j < 128; j += THREADS) {
        ((float4*)(smem + SOFF_WOUT4))[j] =
            make_float4(W_out[j], W_out[128 + j], W_out[256 + j], b_hh[256 + j]);
    }
    __syncthreads();

    // ================= Recurrence (warp-local, no syncthreads) =======================
    const float4* wout4 = (const float4*)(smem + SOFF_WOUT4);
    const uint32_t lane_off = (uint32_t)((lane & 7) * W_STRIDE + ((lane >> 3) & 1) * 16);
    const int r_lo = rowbase + 16 * w + (lane >> 2);
    const int r_hi = r_lo + 8;
    const float* gp_lo = g_gi + (size_t)r_lo * 384;
    const float* gp_hi = g_gi + (size_t)r_hi * 384;
    float* outp_lo = out + (size_t)r_lo * (HORIZON * 3);
    float* outp_hi = out + (size_t)r_hi * (HORIZON * 3);
    const float bo0 = b_out[0], bo1 = b_out[1], bo2 = b_out[2];

    uint32_t A0h[8][4], A0l[8][4], A1h[8][4], A1l[8][4];

    #pragma unroll 1
    for (int t = 0; t < HORIZON; t += 2) {
        gru_step(t, t == 0, A0h, A0l, A1h, A1l, sb, lane_off, lane,
                 gp_lo, gp_hi, wout4, outp_lo, outp_hi, bo0, bo1, bo2);
        gru_step(t + 1, false, A1h, A1l, A0h, A0l, sb, lane_off, lane,
                 gp_lo, gp_hi, wout4, outp_lo, outp_hi, bo0, bo1, bo2);
    }
}

extern "C" void kernel_launch(void* const* d_in, const int* in_sizes, int n_in,
                              void* d_out, int out_size) {
    const float* x     = (const float*)d_in[0];
    const float* W_ih  = (const float*)d_in[1];
    const float* W_hh  = (const float*)d_in[2];
    const float* b_ih  = (const float*)d_in[3];
    const float* b_hh  = (const float*)d_in[4];
    const float* W_out = (const float*)d_in[5];
    const float* b_out = (const float*)d_in[6];
    float* out = (float*)d_out;

    const int B = in_sizes[0] / D_IN;   // 16384
    cudaFuncSetAttribute(gru_hmma_kernel,
                         cudaFuncAttributeMaxDynamicSharedMemorySize, SMEM_BYTES);
    gru_hmma_kernel<<<B / M_TILE, THREADS, SMEM_BYTES>>>(
        x, W_ih, W_hh, b_ih, b_hh, W_out, b_out, out);
}

// round 16
// speedup vs baseline: 1.4200x; 1.0188x over previous
#include <cuda_runtime.h>
#include <cuda_bf16.h>
#include <cstdint>

#define HID 128
#define HORIZON 60
#define THREADS 256
#define D_IN 256
#define M_TILE 128
#define B_TOTAL 16384

#define W_STRIDE 272                 // padded W row: 136 bf16 = 272 B (conflict-free ldmatrix)
#define SOFF_WOUT4 0                 // 128 * float4 {w0,w1,w2,b_hh_n}
#define SOFF_WHI   2048
#define SOFF_WLO   (2048 + 384 * W_STRIDE)
#define SMEM_BYTES (2048 + 2 * 384 * W_STRIDE)   // 210944
#define ST_X 260                     // phase-1 x row stride (floats)

__device__ float g_gi[(size_t)B_TOTAL * 384];    // [row][384]: r,z (+b_ih+b_hh), n (+b_ih)

static __device__ __forceinline__ uint32_t smem_u32(const void* p) {
    uint32_t a;
    asm("{ .reg .u64 t; cvta.to.shared.u64 t, %1; cvt.u32.u64 %0, t; }" : "=r"(a) : "l"(p));
    return a;
}
static __device__ __forceinline__ void ldsm_x4(uint32_t* r, uint32_t addr) {
    asm volatile("ldmatrix.sync.aligned.m8n8.x4.shared.b16 {%0,%1,%2,%3}, [%4];"
        : "=r"(r[0]), "=r"(r[1]), "=r"(r[2]), "=r"(r[3]) : "r"(addr));
}
static __device__ __forceinline__ void mma16816(float* c, const uint32_t* a, const uint32_t* b) {
    asm volatile(
        "mma.sync.aligned.m16n8k16.row.col.f32.bf16.bf16.f32 "
        "{%0,%1,%2,%3}, {%4,%5,%6,%7}, {%8,%9}, {%0,%1,%2,%3};"
        : "+f"(c[0]), "+f"(c[1]), "+f"(c[2]), "+f"(c[3])
        : "r"(a[0]), "r"(a[1]), "r"(a[2]), "r"(a[3]), "r"(b[0]), "r"(b[1]));
}
static __device__ __forceinline__ uint32_t pkbf(float lo, float hi) {   // lo -> bits[0:16)
    uint32_t r;
    asm("cvt.rn.bf16x2.f32 %0, %1, %2;" : "=r"(r) : "f"(hi), "f"(lo));
    return r;
}
static __device__ __forceinline__ float2 unpk2(uint32_t h, uint32_t l) {
    float lo = __bfloat162float(__ushort_as_bfloat16((unsigned short)(h & 0xffff)))
             + __bfloat162float(__ushort_as_bfloat16((unsigned short)(l & 0xffff)));
    float hi = __bfloat162float(__ushort_as_bfloat16((unsigned short)(h >> 16)))
             + __bfloat162float(__ushort_as_bfloat16((unsigned short)(l >> 16)));
    return make_float2(lo, hi);
}
__device__ __forceinline__ float fsig(float x) {
    x = fminf(fmaxf(x, -30.f), 30.f);
    return __fdividef(1.f, 1.f + __expf(-x));
}
__device__ __forceinline__ float ftanh(float x) {
    float a = fabsf(x);
    float e = __expf(-2.f * a);
    float t = __fdividef(1.f - e, 1.f + e);
    return copysignf(t, x);
}

// One GRU step for this warp's 16 rows. Reads A(cur)=h_{t-1} frags, writes A(nxt)=h_t frags.
// j-pair-outer / s-inner loop: only 24 C floats + 8 gin live -> no spills.
static __device__ __forceinline__ void gru_step(
    int t, bool first,
    uint32_t (*Ach)[4], uint32_t (*Acl)[4],
    uint32_t (*Anh)[4], uint32_t (*Anl)[4],
    uint32_t sb, uint32_t lane_off4, int lane,
    const float* gp_lo, const float* gp_hi,
    const float4* wout4, float* outp_lo, float* outp_hi,
    float bo0, float bo1, float bo2)
{
    float pl0 = 0.f, pl1 = 0.f, pl2 = 0.f, ph0 = 0.f, ph1 = 0.f, ph2 = 0.f;

    #pragma unroll
    for (int c = 0; c < 4; c++) {
        #pragma unroll
        for (int h2 = 0; h2 < 2; h2++) {
            const int jb = 32 * c + 16 * h2;
            float C[3][2][4];
            float gin[2][4];
            #pragma unroll
            for (int p = 0; p < 2; p++) {
                int jc = jb + 8 * p + 2 * (lane & 3);
                float2 a0 = *(const float2*)(gp_lo + jc);
                float2 a1 = *(const float2*)(gp_hi + jc);
                C[0][p][0] = a0.x; C[0][p][1] = a0.y; C[0][p][2] = a1.x; C[0][p][3] = a1.y;
                float2 b0 = *(const float2*)(gp_lo + 128 + jc);
                float2 b1 = *(const float2*)(gp_hi + 128 + jc);
                C[1][p][0] = b0.x; C[1][p][1] = b0.y; C[1][p][2] = b1.x; C[1][p][3] = b1.y;
                C[2][p][0] = 0.f; C[2][p][1] = 0.f; C[2][p][2] = 0.f; C[2][p][3] = 0.f;
                float2 n0 = *(const float2*)(gp_lo + 256 + jc);
                float2 n1 = *(const float2*)(gp_hi + 256 + jc);
                gin[p][0] = n0.x; gin[p][1] = n0.y; gin[p][2] = n1.x; gin[p][3] = n1.y;
            }

            if (!first) {
                #pragma unroll
                for (int s = 0; s < 8; s++) {
                    #pragma unroll
                    for (int g = 0; g < 3; g++) {
                        uint32_t off = (uint32_t)((g * 128 + jb) * W_STRIDE + s * 32) + lane_off4;
                        uint32_t bh[4], bl[4];
                        ldsm_x4(bh, sb + SOFF_WHI + off);
                        ldsm_x4(bl, sb + SOFF_WLO + off);
                        mma16816(C[g][0], Ach[s], bh);       // h_hi * W_hi  (jt pair lo)
                        mma16816(C[g][1], Ach[s], bh + 2);   //              (jt pair hi)
                        mma16816(C[g][0], Acl[s], bh);       // h_lo * W_hi
                        mma16816(C[g][1], Acl[s], bh + 2);
                        mma16816(C[g][0], Ach[s], bl);       // h_hi * W_lo
                        mma16816(C[g][1], Ach[s], bl + 2);
                    }
                }
            }

            // epilogue for this j-pair: fills A-frag slot s = 2c + h2 completely
            const int s = 2 * c + h2;
            #pragma unroll
            for (int p = 0; p < 2; p++) {
                int j0 = jb + 8 * p + 2 * (lane & 3);
                float4 w4a = wout4[j0];
                float4 w4b = wout4[j0 + 1];
                int ai = 2 * p;
                float hp[4];
                if (!first) {
                    float2 u0 = unpk2(Ach[s][ai], Acl[s][ai]);
                    float2 u1 = unpk2(Ach[s][ai + 1], Acl[s][ai + 1]);
                    hp[0] = u0.x; hp[1] = u0.y; hp[2] = u1.x; hp[3] = u1.y;
                } else {
                    hp[0] = hp[1] = hp[2] = hp[3] = 0.f;
                }
                float hn[4];
                #pragma unroll
                for (int i = 0; i < 4; i++) {
                    float bhn = (i & 1) ? w4b.w : w4a.w;
                    float r = fsig(C[0][p][i]);
                    float z = fsig(C[1][p][i]);
                    float nn = ftanh(fmaf(r, C[2][p][i] + bhn, gin[p][i]));
                    hn[i] = nn + z * (hp[i] - nn);
                }
                pl0 = fmaf(hn[0], w4a.x, fmaf(hn[1], w4b.x, pl0));
                pl1 = fmaf(hn[0], w4a.y, fmaf(hn[1], w4b.y, pl1));
                pl2 = fmaf(hn[0], w4a.z, fmaf(hn[1], w4b.z, pl2));
                ph0 = fmaf(hn[2], w4a.x, fmaf(hn[3], w4b.x, ph0));
                ph1 = fmaf(hn[2], w4a.y, fmaf(hn[3], w4b.y, ph1));
                ph2 = fmaf(hn[2], w4a.z, fmaf(hn[3], w4b.z, ph2));
                float r0 = hn[0] - __bfloat162float(__float2bfloat16(hn[0]));
                float r1 = hn[1] - __bfloat162float(__float2bfloat16(hn[1]));
                float r2 = hn[2] - __bfloat162float(__float2bfloat16(hn[2]));
                float r3 = hn[3] - __bfloat162float(__float2bfloat16(hn[3]));
                Anh[s][ai]     = pkbf(hn[0], hn[1]);
                Anh[s][ai + 1] = pkbf(hn[2], hn[3]);
                Anl[s][ai]     = pkbf(r0, r1);
                Anl[s][ai + 1] = pkbf(r2, r3);
            }
        }
    }

    #pragma unroll
    for (int m = 1; m <= 2; m <<= 1) {
        pl0 += __shfl_xor_sync(0xFFFFFFFFu, pl0, m);
        pl1 += __shfl_xor_sync(0xFFFFFFFFu, pl1, m);
        pl2 += __shfl_xor_sync(0xFFFFFFFFu, pl2, m);
        ph0 += __shfl_xor_sync(0xFFFFFFFFu, ph0, m);
        ph1 += __shfl_xor_sync(0xFFFFFFFFu, ph1, m);
        ph2 += __shfl_xor_sync(0xFFFFFFFFu, ph2, m);
    }
    if ((lane & 3) == 0) {
        float* o = outp_lo + 3 * t;
        o[0] = pl0 + bo0; o[1] = pl1 + bo1; o[2] = pl2 + bo2;
        float* o2 = outp_hi + 3 * t;
        o2[0] = ph0 + bo0; o2[1] = ph1 + bo1; o2[2] = ph2 + bo2;
    }
}

__global__ void __launch_bounds__(THREADS, 1)
gru_hmma_kernel(const float* __restrict__ x,
                const float* __restrict__ W_ih,
                const float* __restrict__ W_hh,
                const float* __restrict__ b_ih,
                const float* __restrict__ b_hh,
                const float* __restrict__ W_out,
                const float* __restrict__ b_out,
                float* __restrict__ out)
{
    extern __shared__ char smem[];
    float* sx = (float*)smem;                        // phase-1 alias
    const uint32_t sb = smem_u32(smem);
    const int tid = threadIdx.x, lane = tid & 31, w = tid >> 5;
    const int rowbase = blockIdx.x * M_TILE;

    // ================= Phase 1: gi = x @ W_ih^T + biases -> g_gi (SIMT fp32) =========
    for (int idx = tid; idx < M_TILE * (D_IN / 4); idx += THREADS) {
        int row = idx >> 6, c4 = idx & 63;
        *(float4*)&sx[row * ST_X + c4 * 4] =
            ((const float4*)(x + (size_t)rowbase * D_IN))[idx];
    }
    __syncthreads();
    {
        const int tx = tid & 31, ty5 = tid >> 5;
        const int j0 = tx * 4;
        for (int q = 0; q < 4; q++) {
            int r0 = q * 32 + ty5 * 4;
            float acc[4][4][3];
            #pragma unroll
            for (int i = 0; i < 4; i++)
                #pragma unroll
                for (int jj = 0; jj < 4; jj++)
                    #pragma unroll
                    for (int g = 0; g < 3; g++) acc[i][jj][g] = 0.f;
            #pragma unroll 1
            for (int k = 0; k < D_IN; k += 4) {
                float4 xv[4];
                #pragma unroll
                for (int i = 0; i < 4; i++) xv[i] = *(const float4*)&sx[(r0 + i) * ST_X + k];
                #pragma unroll
                for (int g = 0; g < 3; g++) {
                    #pragma unroll
                    for (int jj = 0; jj < 4; jj++) {
                        float4 wv = *(const float4*)&W_ih[(size_t)(g * 128 + j0 + jj) * D_IN + k];
                        #pragma unroll
                        for (int i = 0; i < 4; i++) {
                            float s = acc[i][jj][g];
                            s = fmaf(xv[i].x, wv.x, s);
                            s = fmaf(xv[i].y, wv.y, s);
                            s = fmaf(xv[i].z, wv.z, s);
                            s = fmaf(xv[i].w, wv.w, s);
                            acc[i][jj][g] = s;
                        }
                    }
                }
            }
            #pragma unroll
            for (int i = 0; i < 4; i++) {
                #pragma unroll
                for (int g = 0; g < 3; g++) {
                    float4 st;
                    float* stp = &st.x;
                    #pragma unroll
                    for (int jj = 0; jj < 4; jj++) {
                        float bb = b_ih[g * 128 + j0 + jj] + (g < 2 ? b_hh[g * 128 + j0 + jj] : 0.f);
                        stp[jj] = acc[i][jj][g] + bb;
                    }
                    *(float4*)&g_gi[(size_t)(rowbase + r0 + i) * 384 + g * 128 + j0] = st;
                }
            }
        }
    }
    __syncthreads();

    // ================= Stage W_hh (bf16 hi/lo, padded rows) + wout4 table ============
    for (int idx = tid; idx < 384 * 128; idx += THREADS) {
        int n = idx >> 7, k = idx & 127;
        float wv = W_hh[idx];
        __nv_bfloat16 bh = __float2bfloat16(wv);
        __nv_bfloat16 bl = __float2bfloat16(wv - __bfloat162float(bh));
        *(__nv_bfloat16*)(smem + SOFF_WHI + n * W_STRIDE + k * 2) = bh;
        *(__nv_bfloat16*)(smem + SOFF_WLO + n * W_STRIDE + k * 2) = bl;
    }
    for (int j = tid; j < 128; j += THREADS) {
        ((float4*)(smem + SOFF_WOUT4))[j] =
            make_float4(W_out[j], W_out[128 + j], W_out[256 + j], b_hh[256 + j]);
    }
    __syncthreads();

    // ================= Recurrence (warp-local, no syncthreads) =======================
    const float4* wout4 = (const float4*)(smem + SOFF_WOUT4);
    // ldmatrix.x4 lane mapping: matrices {j+0..7 k-lo, j+0..7 k-hi, j+8..15 k-lo, j+8..15 k-hi}
    const uint32_t lane_off4 = (uint32_t)(((lane & 7) + ((lane >> 4) & 1) * 8) * W_STRIDE
                                          + ((lane >> 3) & 1) * 16);
    const int r_lo = rowbase + 16 * w + (lane >> 2);
    const int r_hi = r_lo + 8;
    const float* gp_lo = g_gi + (size_t)r_lo * 384;
    const float* gp_hi = g_gi + (size_t)r_hi * 384;
    float* outp_lo = out + (size_t)r_lo * (HORIZON * 3);
    float* outp_hi = out + (size_t)r_hi * (HORIZON * 3);
    const float bo0 = b_out[0], bo1 = b_out[1], bo2 = b_out[2];

    uint32_t A0h[8][4], A0l[8][4], A1h[8][4], A1l[8][4];

    #pragma unroll 1
    for (int t = 0; t < HORIZON; t += 2) {
        gru_step(t, t == 0, A0h, A0l, A1h, A1l, sb, lane_off4, lane,
                 gp_lo, gp_hi, wout4, outp_lo, outp_hi, bo0, bo1, bo2);
        gru_step(t + 1, false, A1h, A1l, A0h, A0l, sb, lane_off4, lane,
                 gp_lo, gp_hi, wout4, outp_lo, outp_hi, bo0, bo1, bo2);
    }
}

extern "C" void kernel_launch(void* const* d_in, const int* in_sizes, int n_in,
                              void* d_out, int out_size) {
    const float* x     = (const float*)d_in[0];
    const float* W_ih  = (const float*)d_in[1];
    const float* W_hh  = (const float*)d_in[2];
    const float* b_ih  = (const float*)d_in[3];
    const float* b_hh  = (const float*)d_in[4];
    const float* W_out = (const float*)d_in[5];
    const float* b_out = (const float*)d_in[6];
    float* out = (float*)d_out;

    const int B = in_sizes[0] / D_IN;   // 16384
    cudaFuncSetAttribute(gru_hmma_kernel,
                         cudaFuncAttributeMaxDynamicSharedMemorySize, SMEM_BYTES);
    gru_hmma_kernel<<<B / M_TILE, THREADS, SMEM_BYTES>>>(
        x, W_ih, W_hh, b_ih, b_hh, W_out, b_out, out);
}